// round 2
// baseline (speedup 1.0000x reference)
#include <cuda_runtime.h>
#include <cuda_bf16.h>
#include <cstdint>

#define NN 100000
#define NE 1600000
#define DDIM 128
#define BN_EPS 1e-5f
#define PA 136            // bf16 SMEM row pitch (conflict-free fragment loads)
#define SMEM_BYTES (4 * 128 * PA * 2)   // 4 planes of 128 x PA bf16 = 139264

// ---------------- device scratch (static globals: allowed) ----------------
__device__ float g_h[(size_t)NN * DDIM];
__device__ float g_z[(size_t)NN * DDIM];
__device__ __nv_bfloat16 g_Ahi[(size_t)NN * DDIM];
__device__ __nv_bfloat16 g_Alo[(size_t)NN * DDIM];
__device__ int g_deg[NN];
__device__ int g_off[NN + 1];
__device__ int g_cur[NN];
__device__ int g_srcs[NE];
__device__ int g_eids[NE];
__device__ __nv_bfloat16 g_Whi[3 * 2 * DDIM * DDIM];
__device__ __nv_bfloat16 g_Wlo[3 * 2 * DDIM * DDIM];
__device__ float g_bsum[DDIM];
__device__ float g_bsq[DDIM];

// ---------------- helpers ----------------
__device__ __forceinline__ void split2(float a, float b, uint32_t& hi, uint32_t& lo) {
    __nv_bfloat16 ah = __float2bfloat16(a), bh = __float2bfloat16(b);
    __nv_bfloat16 al = __float2bfloat16(a - __bfloat162float(ah));
    __nv_bfloat16 bl = __float2bfloat16(b - __bfloat162float(bh));
    __nv_bfloat162 H; H.x = ah; H.y = bh;
    __nv_bfloat162 L; L.x = al; L.y = bl;
    hi = *reinterpret_cast<uint32_t*>(&H);
    lo = *reinterpret_cast<uint32_t*>(&L);
}

__device__ __forceinline__ uint32_t lds_u32(const __nv_bfloat16* p) {
    return *reinterpret_cast<const uint32_t*>(p);
}

#define MMA16816(d0,d1,d2,d3,a0,a1,a2,a3,b0,b1)                               \
    asm volatile("mma.sync.aligned.m16n8k16.row.col.f32.bf16.bf16.f32 "       \
                 "{%0,%1,%2,%3},{%4,%5,%6,%7},{%8,%9},{%0,%1,%2,%3};"         \
                 : "+f"(d0), "+f"(d1), "+f"(d2), "+f"(d3)                     \
                 : "r"(a0), "r"(a1), "r"(a2), "r"(a3), "r"(b0), "r"(b1))

// ---------------- setup kernels ----------------
__global__ void k_wsplit(const float* __restrict__ W1, const float* __restrict__ W2) {
    int i = blockIdx.x * blockDim.x + threadIdx.x;
    if (i >= 3 * 2 * DDIM * DDIM) return;
    int m = i / (DDIM * DDIM);
    int l = m >> 1, j = m & 1;
    int within = i - m * DDIM * DDIM;
    float v = (j ? W2 : W1)[l * DDIM * DDIM + within];
    __nv_bfloat16 h = __float2bfloat16(v);
    __nv_bfloat16 lo = __float2bfloat16(v - __bfloat162float(h));
    g_Whi[i] = h; g_Wlo[i] = lo;
}

__global__ void k_zero_deg() {
    int i = blockIdx.x * blockDim.x + threadIdx.x;
    if (i < NN) { g_deg[i] = 0; g_cur[i] = 0; }
}

__global__ void k_hist(const int* __restrict__ dst) {
    int e = blockIdx.x * blockDim.x + threadIdx.x;
    if (e < NE) atomicAdd(&g_deg[__ldg(dst + e)], 1);
}

__global__ void k_scan() {
    __shared__ int wsum[32];
    __shared__ int s_run;
    int tid = threadIdx.x, lane = tid & 31, wid = tid >> 5;
    if (tid == 0) { s_run = 0; g_off[0] = 0; }
    __syncthreads();
    for (int tbase = 0; tbase < NN; tbase += 1024) {
        int i = tbase + tid;
        int v = (i < NN) ? g_deg[i] : 0;
        int x = v;
#pragma unroll
        for (int d = 1; d < 32; d <<= 1) {
            int t = __shfl_up_sync(0xffffffff, x, d);
            if (lane >= d) x += t;
        }
        if (lane == 31) wsum[wid] = x;
        __syncthreads();
        if (wid == 0) {
            int y = wsum[lane];
#pragma unroll
            for (int d = 1; d < 32; d <<= 1) {
                int t = __shfl_up_sync(0xffffffff, y, d);
                if (lane >= d) y += t;
            }
            wsum[lane] = y;
        }
        __syncthreads();
        int incl = x + s_run + (wid ? wsum[wid - 1] : 0);
        if (i < NN) g_off[i + 1] = incl;
        __syncthreads();
        if (tid == 1023) s_run = incl;
        __syncthreads();
    }
}

__global__ void k_scatter(const int* __restrict__ src, const int* __restrict__ dst) {
    int e = blockIdx.x * blockDim.x + threadIdx.x;
    if (e >= NE) return;
    int d = __ldg(dst + e);
    int pos = g_off[d] + atomicAdd(&g_cur[d], 1);
    g_srcs[pos] = __ldg(src + e);
    g_eids[pos] = e;
}

__global__ void k_zero_bn() {
    g_bsum[threadIdx.x] = 0.f;
    g_bsq[threadIdx.x] = 0.f;
}

// ---------------- aggregation: warp per node ----------------
__global__ void k_agg(const float* __restrict__ x, const float* __restrict__ ea,
                      const float* __restrict__ eps, int l, int first) {
    const float* hin = first ? x : g_h;
    int node = (blockIdx.x * blockDim.x + threadIdx.x) >> 5;
    if (node >= NN) return;
    int lane = threadIdx.x & 31;
    int beg = g_off[node], end = g_off[node + 1];
    float4 acc = make_float4(0.f, 0.f, 0.f, 0.f);
    for (int i = beg; i < end; ++i) {
        int s = g_srcs[i];
        int e = g_eids[i];
        float4 hv = ((const float4*)(hin + (size_t)s * DDIM))[lane];
        float4 ev = __ldcs(((const float4*)ea) + (size_t)e * 32 + lane);
        acc.x += fmaxf(hv.x + ev.x, 0.f);
        acc.y += fmaxf(hv.y + ev.y, 0.f);
        acc.z += fmaxf(hv.z + ev.z, 0.f);
        acc.w += fmaxf(hv.w + ev.w, 0.f);
    }
    float el = 1.f + __ldg(eps + l);
    float4 h0 = ((const float4*)(hin + (size_t)node * DDIM))[lane];
    float zx = el * h0.x + acc.x;
    float zy = el * h0.y + acc.y;
    float zz = el * h0.z + acc.z;
    float zw = el * h0.w + acc.w;
    size_t o = (size_t)node * DDIM + lane * 4;
    uint32_t h01, l01, h23, l23;
    split2(zx, zy, h01, l01);
    split2(zz, zw, h23, l23);
    *(uint32_t*)(g_Ahi + o)     = h01;
    *(uint32_t*)(g_Ahi + o + 2) = h23;
    *(uint32_t*)(g_Alo + o)     = l01;
    *(uint32_t*)(g_Alo + o + 2) = l23;
}

// ---------------- fused MLP (2 GEMMs) + residual + BN partials ----------------
__device__ __forceinline__ void gemm_tile(const __nv_bfloat16* __restrict__ sA_hi,
                                          const __nv_bfloat16* __restrict__ sA_lo,
                                          const __nv_bfloat16* __restrict__ sW_hi,
                                          const __nv_bfloat16* __restrict__ sW_lo,
                                          float* acc, int lane, int mrow) {
    uint32_t ah[8][4], al[8][4];
    int r0 = mrow + (lane >> 2);
    int cb = (lane & 3) * 2;
#pragma unroll
    for (int kk = 0; kk < 8; kk++) {
        int c = kk * 16 + cb;
        ah[kk][0] = lds_u32(&sA_hi[r0 * PA + c]);
        ah[kk][1] = lds_u32(&sA_hi[(r0 + 8) * PA + c]);
        ah[kk][2] = lds_u32(&sA_hi[r0 * PA + c + 8]);
        ah[kk][3] = lds_u32(&sA_hi[(r0 + 8) * PA + c + 8]);
        al[kk][0] = lds_u32(&sA_lo[r0 * PA + c]);
        al[kk][1] = lds_u32(&sA_lo[(r0 + 8) * PA + c]);
        al[kk][2] = lds_u32(&sA_lo[r0 * PA + c + 8]);
        al[kk][3] = lds_u32(&sA_lo[(r0 + 8) * PA + c + 8]);
    }
#pragma unroll
    for (int nt = 0; nt < 16; nt++) {
        int bn = nt * 8 + (lane >> 2);
        float* d = acc + nt * 4;
#pragma unroll
        for (int kk = 0; kk < 8; kk++) {
            int bk = kk * 16 + cb;
            uint32_t b0h = lds_u32(&sW_hi[bn * PA + bk]);
            uint32_t b1h = lds_u32(&sW_hi[bn * PA + bk + 8]);
            uint32_t b0l = lds_u32(&sW_lo[bn * PA + bk]);
            uint32_t b1l = lds_u32(&sW_lo[bn * PA + bk + 8]);
            MMA16816(d[0], d[1], d[2], d[3],
                     ah[kk][0], ah[kk][1], ah[kk][2], ah[kk][3], b0h, b1h);
            MMA16816(d[0], d[1], d[2], d[3],
                     al[kk][0], al[kk][1], al[kk][2], al[kk][3], b0h, b1h);
            MMA16816(d[0], d[1], d[2], d[3],
                     ah[kk][0], ah[kk][1], ah[kk][2], ah[kk][3], b0l, b1l);
        }
    }
}

__global__ void __launch_bounds__(256, 1)
k_mlp(int l, const float* __restrict__ x, const float* __restrict__ masks,
      const float* __restrict__ b1g, const float* __restrict__ b2g, int first) {
    const float* xin = first ? x : g_h;
    extern __shared__ char smem[];
    __nv_bfloat16* sAhi = (__nv_bfloat16*)smem;
    __nv_bfloat16* sAlo = sAhi + 128 * PA;
    __nv_bfloat16* sWhi = sAlo + 128 * PA;
    __nv_bfloat16* sWlo = sWhi + 128 * PA;
    float* sZ = (float*)smem;   // reused after GEMM2 (64KB <= 2*34816)

    int tid = threadIdx.x, lane = tid & 31, warp = tid >> 5;
    int base = blockIdx.x * 128;
    int rows = min(128, NN - base);

    // load A (z hi/lo planes), zero-fill OOB rows
    for (int i = tid; i < 128 * 64; i += 256) {
        int r = i >> 6, c2 = i & 63;
        uint32_t vh = 0, vl = 0;
        if (r < rows) {
            size_t gi = (size_t)(base + r) * 64 + c2;
            vh = ((const uint32_t*)g_Ahi)[gi];
            vl = ((const uint32_t*)g_Alo)[gi];
        }
        *(uint32_t*)(sAhi + r * PA + c2 * 2) = vh;
        *(uint32_t*)(sAlo + r * PA + c2 * 2) = vl;
    }
    // load W1 transposed: sW[n][k]
    {
        const __nv_bfloat16* wh = g_Whi + (size_t)(l * 2) * 16384;
        const __nv_bfloat16* wl = g_Wlo + (size_t)(l * 2) * 16384;
        for (int i = tid; i < 16384; i += 256) {
            int k = i >> 7, n = i & 127;
            sWhi[n * PA + k] = wh[i];
            sWlo[n * PA + k] = wl[i];
        }
    }
    __syncthreads();

    float acc[64];
#pragma unroll
    for (int i = 0; i < 64; i++) acc[i] = 0.f;
    int mrow = warp * 16;
    gemm_tile(sAhi, sAlo, sWhi, sWlo, acc, lane, mrow);

    // epilogue 1: relu(acc + b1) -> hi/lo back into sA (own rows only)
    int r0 = mrow + (lane >> 2);
    int cb = (lane & 3) * 2;
#pragma unroll
    for (int nt = 0; nt < 16; nt++) {
        int c = nt * 8 + cb;
        float bb0 = __ldg(b1g + l * 128 + c);
        float bb1 = __ldg(b1g + l * 128 + c + 1);
        float v00 = fmaxf(acc[nt * 4 + 0] + bb0, 0.f);
        float v01 = fmaxf(acc[nt * 4 + 1] + bb1, 0.f);
        float v10 = fmaxf(acc[nt * 4 + 2] + bb0, 0.f);
        float v11 = fmaxf(acc[nt * 4 + 3] + bb1, 0.f);
        uint32_t h0, l0, h1, l1;
        split2(v00, v01, h0, l0);
        split2(v10, v11, h1, l1);
        *(uint32_t*)&sAhi[r0 * PA + c] = h0;
        *(uint32_t*)&sAlo[r0 * PA + c] = l0;
        *(uint32_t*)&sAhi[(r0 + 8) * PA + c] = h1;
        *(uint32_t*)&sAlo[(r0 + 8) * PA + c] = l1;
        acc[nt * 4 + 0] = 0.f; acc[nt * 4 + 1] = 0.f;
        acc[nt * 4 + 2] = 0.f; acc[nt * 4 + 3] = 0.f;
    }
    __syncthreads();
    // load W2 transposed
    {
        const __nv_bfloat16* wh = g_Whi + (size_t)(l * 2 + 1) * 16384;
        const __nv_bfloat16* wl = g_Wlo + (size_t)(l * 2 + 1) * 16384;
        for (int i = tid; i < 16384; i += 256) {
            int k = i >> 7, n = i & 127;
            sWhi[n * PA + k] = wh[i];
            sWlo[n * PA + k] = wl[i];
        }
    }
    __syncthreads();

    gemm_tile(sAhi, sAlo, sWhi, sWlo, acc, lane, mrow);
    __syncthreads();   // everyone done reading sA before sZ overwrite

    // epilogue 2: z = mask * (acc + b2) + x_in
    bool ok0 = (base + r0) < NN;
    bool ok1 = (base + r0 + 8) < NN;
    float m0 = ok0 ? __ldg(masks + (size_t)l * NN + base + r0) : 0.f;
    float m1 = ok1 ? __ldg(masks + (size_t)l * NN + base + r0 + 8) : 0.f;
#pragma unroll
    for (int nt = 0; nt < 16; nt++) {
        int c = nt * 8 + cb;
        float bb0 = __ldg(b2g + l * 128 + c);
        float bb1 = __ldg(b2g + l * 128 + c + 1);
        float2 x0 = ok0 ? *(const float2*)(xin + (size_t)(base + r0) * 128 + c)
                        : make_float2(0.f, 0.f);
        float2 x1 = ok1 ? *(const float2*)(xin + (size_t)(base + r0 + 8) * 128 + c)
                        : make_float2(0.f, 0.f);
        float z00 = m0 * (acc[nt * 4 + 0] + bb0) + x0.x;
        float z01 = m0 * (acc[nt * 4 + 1] + bb1) + x0.y;
        float z10 = m1 * (acc[nt * 4 + 2] + bb0) + x1.x;
        float z11 = m1 * (acc[nt * 4 + 3] + bb1) + x1.y;
        *(float2*)&sZ[r0 * 128 + c] = make_float2(z00, z01);
        *(float2*)&sZ[(r0 + 8) * 128 + c] = make_float2(z10, z11);
    }
    __syncthreads();

    // BN column partials over valid rows
    {
        int c = tid & 127, half = tid >> 7;
        int rbeg = half * 64;
        int rend = min(rbeg + 64, rows);
        float s = 0.f, q = 0.f;
        for (int r = rbeg; r < rend; ++r) {
            float v = sZ[r * 128 + c];
            s += v; q += v * v;
        }
        atomicAdd(&g_bsum[c], s);
        atomicAdd(&g_bsq[c], q);
    }
    // write z tile
    for (int i = tid; i < rows * 32; i += 256) {
        int r = i >> 5, c4 = i & 31;
        ((float4*)(g_z + (size_t)(base + r) * 128))[c4] = ((const float4*)(sZ + r * 128))[c4];
    }
}

// ---------------- BN finalize + apply + relu ----------------
__global__ void k_bn_apply(int l, float* __restrict__ outp,
                           const float* __restrict__ gamma,
                           const float* __restrict__ beta, int last) {
    int idx = blockIdx.x * blockDim.x + threadIdx.x;
    if (idx >= NN * 32) return;
    float* o = last ? outp : g_h;
    int c4 = idx & 31;
    int c = c4 * 4;
    float4 z = ((const float4*)g_z)[idx];
    float invN = 1.f / (float)NN;
    float4 r;
    {
        float mu = g_bsum[c + 0] * invN;
        float var = g_bsq[c + 0] * invN - mu * mu;
        r.x = fmaxf(__ldg(gamma + l * 128 + c + 0) * (z.x - mu) * rsqrtf(var + BN_EPS) + __ldg(beta + l * 128 + c + 0), 0.f);
    }
    {
        float mu = g_bsum[c + 1] * invN;
        float var = g_bsq[c + 1] * invN - mu * mu;
        r.y = fmaxf(__ldg(gamma + l * 128 + c + 1) * (z.y - mu) * rsqrtf(var + BN_EPS) + __ldg(beta + l * 128 + c + 1), 0.f);
    }
    {
        float mu = g_bsum[c + 2] * invN;
        float var = g_bsq[c + 2] * invN - mu * mu;
        r.z = fmaxf(__ldg(gamma + l * 128 + c + 2) * (z.z - mu) * rsqrtf(var + BN_EPS) + __ldg(beta + l * 128 + c + 2), 0.f);
    }
    {
        float mu = g_bsum[c + 3] * invN;
        float var = g_bsq[c + 3] * invN - mu * mu;
        r.w = fmaxf(__ldg(gamma + l * 128 + c + 3) * (z.w - mu) * rsqrtf(var + BN_EPS) + __ldg(beta + l * 128 + c + 3), 0.f);
    }
    ((float4*)o)[idx] = r;
}

// ---------------- launch ----------------
extern "C" void kernel_launch(void* const* d_in, const int* in_sizes, int n_in,
                              void* d_out, int out_size) {
    const float* x     = (const float*)d_in[0];
    const float* ea    = (const float*)d_in[1];
    const float* masks = (const float*)d_in[2];
    const int*   ei    = (const int*)d_in[3];
    const float* eps   = (const float*)d_in[4];
    const float* W1    = (const float*)d_in[5];
    const float* b1    = (const float*)d_in[6];
    const float* W2    = (const float*)d_in[7];
    const float* b2    = (const float*)d_in[8];
    const float* gamma = (const float*)d_in[9];
    const float* beta  = (const float*)d_in[10];
    float* out = (float*)d_out;

    cudaFuncSetAttribute(k_mlp, cudaFuncAttributeMaxDynamicSharedMemorySize, SMEM_BYTES);

    k_wsplit<<<(3 * 2 * DDIM * DDIM + 255) / 256, 256>>>(W1, W2);
    k_zero_deg<<<(NN + 255) / 256, 256>>>();
    k_hist<<<(NE + 255) / 256, 256>>>(ei + NE);
    k_scan<<<1, 1024>>>();
    k_scatter<<<(NE + 255) / 256, 256>>>(ei, ei + NE);

    for (int l = 0; l < 3; l++) {
        int first = (l == 0) ? 1 : 0;
        int last = (l == 2) ? 1 : 0;
        k_zero_bn<<<1, 128>>>();
        k_agg<<<(NN + 7) / 8, 256>>>(x, ea, eps, l, first);
        k_mlp<<<782, 256, SMEM_BYTES>>>(l, x, masks, b1, b2, first);
        k_bn_apply<<<(NN * 32 + 255) / 256, 256>>>(l, out, gamma, beta, last);
    }
}

// round 3
// speedup vs baseline: 1.1687x; 1.1687x over previous
#include <cuda_runtime.h>
#include <cuda_bf16.h>
#include <cstdint>

#define NN 100000
#define NE 1600000
#define DDIM 128
#define BN_EPS 1e-5f
#define PA 136            // bf16 SMEM row pitch (conflict-free fragment loads)
#define SMEM_BYTES (4 * 128 * PA * 2)   // 4 planes of 128 x PA bf16 = 139264
#define SCAN_NB ((NN + 1023) / 1024)    // 98

// ---------------- device scratch (static globals: allowed) ----------------
__device__ float g_h[(size_t)NN * DDIM];
__device__ float g_z[(size_t)NN * DDIM];
__device__ __nv_bfloat16 g_Ahi[(size_t)NN * DDIM];
__device__ __nv_bfloat16 g_Alo[(size_t)NN * DDIM];
__device__ int g_deg[NN];
__device__ int g_off[NN + 1];
__device__ int g_cur[NN];
__device__ int2 g_se[NE];
__device__ int g_btot[SCAN_NB];
__device__ __nv_bfloat16 g_Whi[3 * 2 * DDIM * DDIM];
__device__ __nv_bfloat16 g_Wlo[3 * 2 * DDIM * DDIM];
__device__ float g_bsum[3][DDIM];
__device__ float g_bsq[3][DDIM];

// ---------------- helpers ----------------
__device__ __forceinline__ void split2(float a, float b, uint32_t& hi, uint32_t& lo) {
    __nv_bfloat16 ah = __float2bfloat16(a), bh = __float2bfloat16(b);
    __nv_bfloat16 al = __float2bfloat16(a - __bfloat162float(ah));
    __nv_bfloat16 bl = __float2bfloat16(b - __bfloat162float(bh));
    __nv_bfloat162 H; H.x = ah; H.y = bh;
    __nv_bfloat162 L; L.x = al; L.y = bl;
    hi = *reinterpret_cast<uint32_t*>(&H);
    lo = *reinterpret_cast<uint32_t*>(&L);
}

__device__ __forceinline__ uint32_t lds_u32(const __nv_bfloat16* p) {
    return *reinterpret_cast<const uint32_t*>(p);
}

#define MMA16816(d0,d1,d2,d3,a0,a1,a2,a3,b0,b1)                               \
    asm volatile("mma.sync.aligned.m16n8k16.row.col.f32.bf16.bf16.f32 "       \
                 "{%0,%1,%2,%3},{%4,%5,%6,%7},{%8,%9},{%0,%1,%2,%3};"         \
                 : "+f"(d0), "+f"(d1), "+f"(d2), "+f"(d3)                     \
                 : "r"(a0), "r"(a1), "r"(a2), "r"(a3), "r"(b0), "r"(b1))

// ---------------- fused setup: W split + zero deg/cur + zero BN accum ------
__global__ void k_setup(const float* __restrict__ W1, const float* __restrict__ W2) {
    int i = blockIdx.x * blockDim.x + threadIdx.x;
    if (i < 3 * 2 * DDIM * DDIM) {
        int m = i / (DDIM * DDIM);
        int l = m >> 1, j = m & 1;
        int within = i - m * DDIM * DDIM;
        float v = (j ? W2 : W1)[l * DDIM * DDIM + within];
        __nv_bfloat16 h = __float2bfloat16(v);
        __nv_bfloat16 lo = __float2bfloat16(v - __bfloat162float(h));
        g_Whi[i] = h; g_Wlo[i] = lo;
    }
    if (i < NN) { g_deg[i] = 0; g_cur[i] = 0; }
    if (i < 3 * DDIM) {
        ((float*)g_bsum)[i] = 0.f;
        ((float*)g_bsq)[i] = 0.f;
    }
}

__global__ void k_hist(const int* __restrict__ dst) {
    int e = blockIdx.x * blockDim.x + threadIdx.x;
    if (e < NE) atomicAdd(&g_deg[__ldg(dst + e)], 1);
}

// ---------------- two-level scan ----------------
__global__ void k_scan1() {
    __shared__ int wsum[32];
    int tid = threadIdx.x, lane = tid & 31, wid = tid >> 5;
    int i = blockIdx.x * 1024 + tid;
    int v = (i < NN) ? g_deg[i] : 0;
    int x = v;
#pragma unroll
    for (int d = 1; d < 32; d <<= 1) {
        int t = __shfl_up_sync(0xffffffff, x, d);
        if (lane >= d) x += t;
    }
    if (lane == 31) wsum[wid] = x;
    __syncthreads();
    if (wid == 0) {
        int y = wsum[lane];
#pragma unroll
        for (int d = 1; d < 32; d <<= 1) {
            int t = __shfl_up_sync(0xffffffff, y, d);
            if (lane >= d) y += t;
        }
        wsum[lane] = y;
    }
    __syncthreads();
    int incl = x + (wid ? wsum[wid - 1] : 0);
    if (i < NN) g_off[i + 1] = incl;
    if (tid == 1023) g_btot[blockIdx.x] = incl;
}

__global__ void k_scan2() {   // 1 block, 128 threads, scans SCAN_NB totals
    __shared__ int ws[4];
    int tid = threadIdx.x, lane = tid & 31, wid = tid >> 5;
    int v = (tid < SCAN_NB) ? g_btot[tid] : 0;
    int x = v;
#pragma unroll
    for (int d = 1; d < 32; d <<= 1) {
        int t = __shfl_up_sync(0xffffffff, x, d);
        if (lane >= d) x += t;
    }
    if (lane == 31) ws[wid] = x;
    __syncthreads();
    if (tid == 0) {
        int r = 0;
#pragma unroll
        for (int j = 0; j < 4; j++) { int t = ws[j]; ws[j] = r; r += t; }
    }
    __syncthreads();
    int incl = x + ws[wid];
    if (tid < SCAN_NB) g_btot[tid] = incl - v;   // exclusive
}

__global__ void k_scan3() {
    int i = blockIdx.x * blockDim.x + threadIdx.x;
    if (i == 0) g_off[0] = 0;
    if (i < NN) g_off[i + 1] += g_btot[i >> 10];
}

__global__ void k_scatter(const int* __restrict__ src, const int* __restrict__ dst) {
    int e = blockIdx.x * blockDim.x + threadIdx.x;
    if (e >= NE) return;
    int d = __ldg(dst + e);
    int pos = g_off[d] + atomicAdd(&g_cur[d], 1);
    g_se[pos] = make_int2(__ldg(src + e), e);
}

// ---------------- aggregation: warp per node, 2x unrolled ----------------
__global__ void k_agg(const float* __restrict__ x, const float* __restrict__ ea,
                      const float* __restrict__ eps, int l, int first) {
    const float* hin = first ? x : g_h;
    int node = (blockIdx.x * blockDim.x + threadIdx.x) >> 5;
    if (node >= NN) return;
    int lane = threadIdx.x & 31;
    int beg = g_off[node], end = g_off[node + 1];
    float4 acc = make_float4(0.f, 0.f, 0.f, 0.f);
    int i = beg;
    for (; i + 2 <= end; i += 2) {
        int2 a = g_se[i];
        int2 b = g_se[i + 1];
        float4 h0 = ((const float4*)(hin + (size_t)a.x * DDIM))[lane];
        float4 e0 = __ldcs(((const float4*)ea) + (size_t)a.y * 32 + lane);
        float4 h1 = ((const float4*)(hin + (size_t)b.x * DDIM))[lane];
        float4 e1 = __ldcs(((const float4*)ea) + (size_t)b.y * 32 + lane);
        acc.x += fmaxf(h0.x + e0.x, 0.f) + fmaxf(h1.x + e1.x, 0.f);
        acc.y += fmaxf(h0.y + e0.y, 0.f) + fmaxf(h1.y + e1.y, 0.f);
        acc.z += fmaxf(h0.z + e0.z, 0.f) + fmaxf(h1.z + e1.z, 0.f);
        acc.w += fmaxf(h0.w + e0.w, 0.f) + fmaxf(h1.w + e1.w, 0.f);
    }
    if (i < end) {
        int2 a = g_se[i];
        float4 h0 = ((const float4*)(hin + (size_t)a.x * DDIM))[lane];
        float4 e0 = __ldcs(((const float4*)ea) + (size_t)a.y * 32 + lane);
        acc.x += fmaxf(h0.x + e0.x, 0.f);
        acc.y += fmaxf(h0.y + e0.y, 0.f);
        acc.z += fmaxf(h0.z + e0.z, 0.f);
        acc.w += fmaxf(h0.w + e0.w, 0.f);
    }
    float el = 1.f + __ldg(eps + l);
    float4 h0 = ((const float4*)(hin + (size_t)node * DDIM))[lane];
    float zx = el * h0.x + acc.x;
    float zy = el * h0.y + acc.y;
    float zz = el * h0.z + acc.z;
    float zw = el * h0.w + acc.w;
    size_t o = (size_t)node * DDIM + lane * 4;
    uint32_t h01, l01, h23, l23;
    split2(zx, zy, h01, l01);
    split2(zz, zw, h23, l23);
    *(uint32_t*)(g_Ahi + o)     = h01;
    *(uint32_t*)(g_Ahi + o + 2) = h23;
    *(uint32_t*)(g_Alo + o)     = l01;
    *(uint32_t*)(g_Alo + o + 2) = l23;
}

// ---------------- fused MLP (2 GEMMs) + residual + BN partials ----------------
__device__ __forceinline__ void gemm_tile(const __nv_bfloat16* __restrict__ sA_hi,
                                          const __nv_bfloat16* __restrict__ sA_lo,
                                          const __nv_bfloat16* __restrict__ sW_hi,
                                          const __nv_bfloat16* __restrict__ sW_lo,
                                          float* acc, int lane, int mrow) {
    uint32_t ah[8][4], al[8][4];
    int r0 = mrow + (lane >> 2);
    int cb = (lane & 3) * 2;
#pragma unroll
    for (int kk = 0; kk < 8; kk++) {
        int c = kk * 16 + cb;
        ah[kk][0] = lds_u32(&sA_hi[r0 * PA + c]);
        ah[kk][1] = lds_u32(&sA_hi[(r0 + 8) * PA + c]);
        ah[kk][2] = lds_u32(&sA_hi[r0 * PA + c + 8]);
        ah[kk][3] = lds_u32(&sA_hi[(r0 + 8) * PA + c + 8]);
        al[kk][0] = lds_u32(&sA_lo[r0 * PA + c]);
        al[kk][1] = lds_u32(&sA_lo[(r0 + 8) * PA + c]);
        al[kk][2] = lds_u32(&sA_lo[r0 * PA + c + 8]);
        al[kk][3] = lds_u32(&sA_lo[(r0 + 8) * PA + c + 8]);
    }
#pragma unroll
    for (int nt = 0; nt < 16; nt++) {
        int bn = nt * 8 + (lane >> 2);
        float* d = acc + nt * 4;
#pragma unroll
        for (int kk = 0; kk < 8; kk++) {
            int bk = kk * 16 + cb;
            uint32_t b0h = lds_u32(&sW_hi[bn * PA + bk]);
            uint32_t b1h = lds_u32(&sW_hi[bn * PA + bk + 8]);
            uint32_t b0l = lds_u32(&sW_lo[bn * PA + bk]);
            uint32_t b1l = lds_u32(&sW_lo[bn * PA + bk + 8]);
            MMA16816(d[0], d[1], d[2], d[3],
                     ah[kk][0], ah[kk][1], ah[kk][2], ah[kk][3], b0h, b1h);
            MMA16816(d[0], d[1], d[2], d[3],
                     al[kk][0], al[kk][1], al[kk][2], al[kk][3], b0h, b1h);
            MMA16816(d[0], d[1], d[2], d[3],
                     ah[kk][0], ah[kk][1], ah[kk][2], ah[kk][3], b0l, b1l);
        }
    }
}

__global__ void __launch_bounds__(256, 1)
k_mlp(int l, const float* __restrict__ x, const float* __restrict__ masks,
      const float* __restrict__ b1g, const float* __restrict__ b2g, int first) {
    const float* xin = first ? x : g_h;
    extern __shared__ char smem[];
    __nv_bfloat16* sAhi = (__nv_bfloat16*)smem;
    __nv_bfloat16* sAlo = sAhi + 128 * PA;
    __nv_bfloat16* sWhi = sAlo + 128 * PA;
    __nv_bfloat16* sWlo = sWhi + 128 * PA;
    float* sZ = (float*)smem;   // reused after GEMM2 (64KB <= 2*34816)

    int tid = threadIdx.x, lane = tid & 31, warp = tid >> 5;
    int base = blockIdx.x * 128;
    int rows = min(128, NN - base);

    // load A (z hi/lo planes), zero-fill OOB rows
    for (int i = tid; i < 128 * 64; i += 256) {
        int r = i >> 6, c2 = i & 63;
        uint32_t vh = 0, vl = 0;
        if (r < rows) {
            size_t gi = (size_t)(base + r) * 64 + c2;
            vh = ((const uint32_t*)g_Ahi)[gi];
            vl = ((const uint32_t*)g_Alo)[gi];
        }
        *(uint32_t*)(sAhi + r * PA + c2 * 2) = vh;
        *(uint32_t*)(sAlo + r * PA + c2 * 2) = vl;
    }
    // load W1 transposed: sW[n][k]
    {
        const __nv_bfloat16* wh = g_Whi + (size_t)(l * 2) * 16384;
        const __nv_bfloat16* wl = g_Wlo + (size_t)(l * 2) * 16384;
        for (int i = tid; i < 16384; i += 256) {
            int k = i >> 7, n = i & 127;
            sWhi[n * PA + k] = wh[i];
            sWlo[n * PA + k] = wl[i];
        }
    }
    __syncthreads();

    float acc[64];
#pragma unroll
    for (int i = 0; i < 64; i++) acc[i] = 0.f;
    int mrow = warp * 16;
    gemm_tile(sAhi, sAlo, sWhi, sWlo, acc, lane, mrow);

    // epilogue 1: relu(acc + b1) -> hi/lo back into sA (own rows only)
    int r0 = mrow + (lane >> 2);
    int cb = (lane & 3) * 2;
#pragma unroll
    for (int nt = 0; nt < 16; nt++) {
        int c = nt * 8 + cb;
        float bb0 = __ldg(b1g + l * 128 + c);
        float bb1 = __ldg(b1g + l * 128 + c + 1);
        float v00 = fmaxf(acc[nt * 4 + 0] + bb0, 0.f);
        float v01 = fmaxf(acc[nt * 4 + 1] + bb1, 0.f);
        float v10 = fmaxf(acc[nt * 4 + 2] + bb0, 0.f);
        float v11 = fmaxf(acc[nt * 4 + 3] + bb1, 0.f);
        uint32_t h0, l0, h1, l1;
        split2(v00, v01, h0, l0);
        split2(v10, v11, h1, l1);
        *(uint32_t*)&sAhi[r0 * PA + c] = h0;
        *(uint32_t*)&sAlo[r0 * PA + c] = l0;
        *(uint32_t*)&sAhi[(r0 + 8) * PA + c] = h1;
        *(uint32_t*)&sAlo[(r0 + 8) * PA + c] = l1;
        acc[nt * 4 + 0] = 0.f; acc[nt * 4 + 1] = 0.f;
        acc[nt * 4 + 2] = 0.f; acc[nt * 4 + 3] = 0.f;
    }
    __syncthreads();
    // load W2 transposed
    {
        const __nv_bfloat16* wh = g_Whi + (size_t)(l * 2 + 1) * 16384;
        const __nv_bfloat16* wl = g_Wlo + (size_t)(l * 2 + 1) * 16384;
        for (int i = tid; i < 16384; i += 256) {
            int k = i >> 7, n = i & 127;
            sWhi[n * PA + k] = wh[i];
            sWlo[n * PA + k] = wl[i];
        }
    }
    __syncthreads();

    gemm_tile(sAhi, sAlo, sWhi, sWlo, acc, lane, mrow);
    __syncthreads();   // everyone done reading sA before sZ overwrite

    // epilogue 2: z = mask * (acc + b2) + x_in
    bool ok0 = (base + r0) < NN;
    bool ok1 = (base + r0 + 8) < NN;
    float m0 = ok0 ? __ldg(masks + (size_t)l * NN + base + r0) : 0.f;
    float m1 = ok1 ? __ldg(masks + (size_t)l * NN + base + r0 + 8) : 0.f;
#pragma unroll
    for (int nt = 0; nt < 16; nt++) {
        int c = nt * 8 + cb;
        float bb0 = __ldg(b2g + l * 128 + c);
        float bb1 = __ldg(b2g + l * 128 + c + 1);
        float2 x0 = ok0 ? *(const float2*)(xin + (size_t)(base + r0) * 128 + c)
                        : make_float2(0.f, 0.f);
        float2 x1 = ok1 ? *(const float2*)(xin + (size_t)(base + r0 + 8) * 128 + c)
                        : make_float2(0.f, 0.f);
        float z00 = m0 * (acc[nt * 4 + 0] + bb0) + x0.x;
        float z01 = m0 * (acc[nt * 4 + 1] + bb1) + x0.y;
        float z10 = m1 * (acc[nt * 4 + 2] + bb0) + x1.x;
        float z11 = m1 * (acc[nt * 4 + 3] + bb1) + x1.y;
        *(float2*)&sZ[r0 * 128 + c] = make_float2(z00, z01);
        *(float2*)&sZ[(r0 + 8) * 128 + c] = make_float2(z10, z11);
    }
    __syncthreads();

    // BN column partials over valid rows
    {
        int c = tid & 127, half = tid >> 7;
        int rbeg = half * 64;
        int rend = min(rbeg + 64, rows);
        float s = 0.f, q = 0.f;
        for (int r = rbeg; r < rend; ++r) {
            float v = sZ[r * 128 + c];
            s += v; q += v * v;
        }
        atomicAdd(&g_bsum[l][c], s);
        atomicAdd(&g_bsq[l][c], q);
    }
    // write z tile
    for (int i = tid; i < rows * 32; i += 256) {
        int r = i >> 5, c4 = i & 31;
        ((float4*)(g_z + (size_t)(base + r) * 128))[c4] = ((const float4*)(sZ + r * 128))[c4];
    }
}

// ---------------- BN finalize + apply + relu ----------------
__global__ void k_bn_apply(int l, float* __restrict__ outp,
                           const float* __restrict__ gamma,
                           const float* __restrict__ beta, int last) {
    int idx = blockIdx.x * blockDim.x + threadIdx.x;
    if (idx >= NN * 32) return;
    float* o = last ? outp : g_h;
    int c4 = idx & 31;
    int c = c4 * 4;
    float4 z = ((const float4*)g_z)[idx];
    float invN = 1.f / (float)NN;
    float4 r;
    {
        float mu = g_bsum[l][c + 0] * invN;
        float var = g_bsq[l][c + 0] * invN - mu * mu;
        r.x = fmaxf(__ldg(gamma + l * 128 + c + 0) * (z.x - mu) * rsqrtf(var + BN_EPS) + __ldg(beta + l * 128 + c + 0), 0.f);
    }
    {
        float mu = g_bsum[l][c + 1] * invN;
        float var = g_bsq[l][c + 1] * invN - mu * mu;
        r.y = fmaxf(__ldg(gamma + l * 128 + c + 1) * (z.y - mu) * rsqrtf(var + BN_EPS) + __ldg(beta + l * 128 + c + 1), 0.f);
    }
    {
        float mu = g_bsum[l][c + 2] * invN;
        float var = g_bsq[l][c + 2] * invN - mu * mu;
        r.z = fmaxf(__ldg(gamma + l * 128 + c + 2) * (z.z - mu) * rsqrtf(var + BN_EPS) + __ldg(beta + l * 128 + c + 2), 0.f);
    }
    {
        float mu = g_bsum[l][c + 3] * invN;
        float var = g_bsq[l][c + 3] * invN - mu * mu;
        r.w = fmaxf(__ldg(gamma + l * 128 + c + 3) * (z.w - mu) * rsqrtf(var + BN_EPS) + __ldg(beta + l * 128 + c + 3), 0.f);
    }
    ((float4*)o)[idx] = r;
}

// ---------------- launch ----------------
extern "C" void kernel_launch(void* const* d_in, const int* in_sizes, int n_in,
                              void* d_out, int out_size) {
    const float* x     = (const float*)d_in[0];
    const float* ea    = (const float*)d_in[1];
    const float* masks = (const float*)d_in[2];
    const int*   ei    = (const int*)d_in[3];
    const float* eps   = (const float*)d_in[4];
    const float* W1    = (const float*)d_in[5];
    const float* b1    = (const float*)d_in[6];
    const float* W2    = (const float*)d_in[7];
    const float* b2    = (const float*)d_in[8];
    const float* gamma = (const float*)d_in[9];
    const float* beta  = (const float*)d_in[10];
    float* out = (float*)d_out;

    cudaFuncSetAttribute(k_mlp, cudaFuncAttributeMaxDynamicSharedMemorySize, SMEM_BYTES);

    k_setup<<<(NN + 255) / 256, 256>>>(W1, W2);
    k_hist<<<(NE + 255) / 256, 256>>>(ei + NE);
    k_scan1<<<SCAN_NB, 1024>>>();
    k_scan2<<<1, 128>>>();
    k_scan3<<<(NN + 255) / 256, 256>>>();
    k_scatter<<<(NE + 255) / 256, 256>>>(ei, ei + NE);

    for (int l = 0; l < 3; l++) {
        int first = (l == 0) ? 1 : 0;
        int last = (l == 2) ? 1 : 0;
        k_agg<<<(NN + 7) / 8, 256>>>(x, ea, eps, l, first);
        k_mlp<<<782, 256, SMEM_BYTES>>>(l, x, masks, b1, b2, first);
        k_bn_apply<<<(NN * 32 + 255) / 256, 256>>>(l, out, gamma, beta, last);
    }
}